// round 1
// baseline (speedup 1.0000x reference)
#include <cuda_runtime.h>
#include <math.h>

#define BATCH 4096
#define DIM   1024
#define LN_EPS 1e-5f

// ---------------- scratch (static device globals; no runtime allocation) ----
__device__ float g_q [(size_t)BATCH * DIM];
__device__ float g_k [(size_t)BATCH * DIM];
__device__ float g_v [(size_t)BATCH * DIM];
__device__ float g_av[(size_t)BATCH * DIM];
__device__ float g_h [(size_t)BATCH * DIM];
__device__ float g_s [(size_t)BATCH * BATCH];

// ---------------- tiled fp32 GEMM: C[M,N] = alpha * A[M,K] x B(^T) ----------
// BT=true : B is [N,K] row-major (NT gemm, C=A*B^T)
// BT=false: B is [K,N] row-major (NN gemm, C=A*B)
// SCALE: multiply by alpha.  EPI: += bias[col] + resid[row,col]
// Tiling: 128x128x8, 256 threads, 8x8 micro-tile per thread.
// All dims used here are multiples of 128 (M,N) and 8 (K) -> no edge guards.
template<bool BT, bool SCALE, bool EPI>
__global__ __launch_bounds__(256) void gemm128(
    const float* __restrict__ A, const float* __restrict__ B,
    float* __restrict__ C, int M, int N, int K, float alpha,
    const float* __restrict__ bias, const float* __restrict__ resid)
{
    __shared__ float As[8][128];
    __shared__ float Bs[8][128];

    const int tid = threadIdx.x;
    const int tx  = tid & 15;        // 0..15  -> col group
    const int ty  = tid >> 4;        // 0..15  -> row group
    const int lr  = tid >> 1;        // 0..127 (K-major tile loads)
    const int lc  = (tid & 1) * 4;   // 0 or 4
    const int brow = tid >> 5;       // 0..7   (NN B tile loads)
    const int bcol = (tid & 31) * 4; // 0..124

    const float* Ab = A + (size_t)blockIdx.y * 128 * K;

    float acc[8][8];
    #pragma unroll
    for (int i = 0; i < 8; i++)
        #pragma unroll
        for (int j = 0; j < 8; j++) acc[i][j] = 0.f;

    for (int k0 = 0; k0 < K; k0 += 8) {
        // stage A tile (transpose into K-major smem)
        float4 a4 = *reinterpret_cast<const float4*>(Ab + (size_t)lr * K + k0 + lc);
        As[lc + 0][lr] = a4.x; As[lc + 1][lr] = a4.y;
        As[lc + 2][lr] = a4.z; As[lc + 3][lr] = a4.w;

        if (BT) {
            const float* Bb = B + (size_t)blockIdx.x * 128 * K;
            float4 b4 = *reinterpret_cast<const float4*>(Bb + (size_t)lr * K + k0 + lc);
            Bs[lc + 0][lr] = b4.x; Bs[lc + 1][lr] = b4.y;
            Bs[lc + 2][lr] = b4.z; Bs[lc + 3][lr] = b4.w;
        } else {
            float4 b4 = *reinterpret_cast<const float4*>(
                B + (size_t)(k0 + brow) * N + (size_t)blockIdx.x * 128 + bcol);
            *reinterpret_cast<float4*>(&Bs[brow][bcol]) = b4;
        }
        __syncthreads();

        #pragma unroll
        for (int kk = 0; kk < 8; kk++) {
            float4 a0 = *reinterpret_cast<const float4*>(&As[kk][ty * 8]);
            float4 a1 = *reinterpret_cast<const float4*>(&As[kk][ty * 8 + 4]);
            float4 b0 = *reinterpret_cast<const float4*>(&Bs[kk][tx * 8]);
            float4 b1 = *reinterpret_cast<const float4*>(&Bs[kk][tx * 8 + 4]);
            float a[8] = {a0.x, a0.y, a0.z, a0.w, a1.x, a1.y, a1.z, a1.w};
            float b[8] = {b0.x, b0.y, b0.z, b0.w, b1.x, b1.y, b1.z, b1.w};
            #pragma unroll
            for (int i = 0; i < 8; i++)
                #pragma unroll
                for (int j = 0; j < 8; j++)
                    acc[i][j] = fmaf(a[i], b[j], acc[i][j]);
        }
        __syncthreads();
    }

    const int r0 = blockIdx.y * 128 + ty * 8;
    const int c0 = blockIdx.x * 128 + tx * 8;
    #pragma unroll
    for (int i = 0; i < 8; i++) {
        #pragma unroll
        for (int j = 0; j < 8; j++) {
            float v = acc[i][j];
            if (SCALE) v *= alpha;
            if (EPI)   v += bias[c0 + j] + resid[(size_t)(r0 + i) * N + c0 + j];
            C[(size_t)(r0 + i) * N + c0 + j] = v;
        }
    }
}

// ---------------- row softmax over 4096 columns, one block per row ----------
__global__ __launch_bounds__(256) void softmax_rows(float* __restrict__ S)
{
    __shared__ float red[8];
    const int tid = threadIdx.x;
    float* p = S + (size_t)blockIdx.x * BATCH;

    float4 v[4];
    float m = -1e30f;
    #pragma unroll
    for (int i = 0; i < 4; i++) {
        v[i] = *reinterpret_cast<const float4*>(p + (size_t)(i * 256 + tid) * 4);
        m = fmaxf(m, fmaxf(fmaxf(v[i].x, v[i].y), fmaxf(v[i].z, v[i].w)));
    }
    #pragma unroll
    for (int o = 16; o; o >>= 1) m = fmaxf(m, __shfl_xor_sync(0xffffffffu, m, o));
    if ((tid & 31) == 0) red[tid >> 5] = m;
    __syncthreads();
    m = red[0];
    #pragma unroll
    for (int i = 1; i < 8; i++) m = fmaxf(m, red[i]);
    __syncthreads();

    float s = 0.f;
    #pragma unroll
    for (int i = 0; i < 4; i++) {
        v[i].x = __expf(v[i].x - m); v[i].y = __expf(v[i].y - m);
        v[i].z = __expf(v[i].z - m); v[i].w = __expf(v[i].w - m);
        s += v[i].x + v[i].y + v[i].z + v[i].w;
    }
    #pragma unroll
    for (int o = 16; o; o >>= 1) s += __shfl_xor_sync(0xffffffffu, s, o);
    if ((tid & 31) == 0) red[tid >> 5] = s;
    __syncthreads();
    s = red[0];
    #pragma unroll
    for (int i = 1; i < 8; i++) s += red[i];
    const float r = 1.f / s;

    #pragma unroll
    for (int i = 0; i < 4; i++) {
        v[i].x *= r; v[i].y *= r; v[i].z *= r; v[i].w *= r;
        *reinterpret_cast<float4*>(p + (size_t)(i * 256 + tid) * 4) = v[i];
    }
}

// ---------------- layernorm over 1024 columns, one block per row ------------
__global__ __launch_bounds__(256) void layernorm_rows(
    const float* __restrict__ H, const float* __restrict__ gamma,
    const float* __restrict__ beta, float* __restrict__ out)
{
    __shared__ float redS[8], redQ[8];
    const int tid = threadIdx.x;
    const float* p = H + (size_t)blockIdx.x * DIM;

    float4 v = *reinterpret_cast<const float4*>(p + tid * 4);
    float s  = v.x + v.y + v.z + v.w;
    float ss = v.x * v.x + v.y * v.y + v.z * v.z + v.w * v.w;
    #pragma unroll
    for (int o = 16; o; o >>= 1) {
        s  += __shfl_xor_sync(0xffffffffu, s, o);
        ss += __shfl_xor_sync(0xffffffffu, ss, o);
    }
    if ((tid & 31) == 0) { redS[tid >> 5] = s; redQ[tid >> 5] = ss; }
    __syncthreads();
    s = 0.f; ss = 0.f;
    #pragma unroll
    for (int i = 0; i < 8; i++) { s += redS[i]; ss += redQ[i]; }

    const float mu  = s * (1.f / DIM);
    const float var = ss * (1.f / DIM) - mu * mu;
    const float rs  = rsqrtf(var + LN_EPS);

    float4 g = *reinterpret_cast<const float4*>(gamma + tid * 4);
    float4 b = *reinterpret_cast<const float4*>(beta  + tid * 4);
    float4 o;
    o.x = (v.x - mu) * rs * g.x + b.x;
    o.y = (v.y - mu) * rs * g.y + b.y;
    o.z = (v.z - mu) * rs * g.z + b.z;
    o.w = (v.w - mu) * rs * g.w + b.w;
    *reinterpret_cast<float4*>(out + (size_t)blockIdx.x * DIM + tid * 4) = o;
}

// ---------------- launch --------------------------------------------------
extern "C" void kernel_launch(void* const* d_in, const int* in_sizes, int n_in,
                              void* d_out, int out_size)
{
    const float* x     = (const float*)d_in[0];
    const float* Wq    = (const float*)d_in[1];
    const float* Wk    = (const float*)d_in[2];
    const float* Wv    = (const float*)d_in[3];
    const float* fcw   = (const float*)d_in[4];
    const float* fcb   = (const float*)d_in[5];
    const float* gamma = (const float*)d_in[6];
    const float* beta  = (const float*)d_in[7];
    float* out = (float*)d_out;

    float *q, *k, *v, *s, *av, *h;
    cudaGetSymbolAddress((void**)&q,  g_q);
    cudaGetSymbolAddress((void**)&k,  g_k);
    cudaGetSymbolAddress((void**)&v,  g_v);
    cudaGetSymbolAddress((void**)&s,  g_s);
    cudaGetSymbolAddress((void**)&av, g_av);
    cudaGetSymbolAddress((void**)&h,  g_h);

    const dim3 blk(256);
    const dim3 gQKV(DIM / 128, BATCH / 128);     // 8 x 32
    const dim3 gS(BATCH / 128, BATCH / 128);     // 32 x 32

    // Q, K, V projections: C = x @ W^T   (NT)
    gemm128<true,  false, false><<<gQKV, blk>>>(x, Wq, q, BATCH, DIM, DIM, 1.f, nullptr, nullptr);
    gemm128<true,  false, false><<<gQKV, blk>>>(x, Wk, k, BATCH, DIM, DIM, 1.f, nullptr, nullptr);
    gemm128<true,  false, false><<<gQKV, blk>>>(x, Wv, v, BATCH, DIM, DIM, 1.f, nullptr, nullptr);

    // scores = (K @ Q^T) / sqrt(d)   (NT, scaled)
    gemm128<true,  true,  false><<<gS, blk>>>(k, q, s, BATCH, BATCH, DIM, 0.03125f, nullptr, nullptr);

    // row softmax
    softmax_rows<<<BATCH, blk>>>(s);

    // x_adapted = attn @ V   (NN)
    gemm128<false, false, false><<<gQKV, blk>>>(s, v, av, BATCH, DIM, BATCH, 1.f, nullptr, nullptr);

    // h = x_adapted @ fc_w^T + fc_b + x   (NT + fused bias/residual epilogue)
    gemm128<true,  false, true ><<<gQKV, blk>>>(av, fcw, h, BATCH, DIM, DIM, 1.f, fcb, x);

    // layernorm -> output
    layernorm_rows<<<BATCH, blk>>>(h, gamma, beta, out);
}

// round 3
// speedup vs baseline: 2.5844x; 2.5844x over previous
#include <cuda_runtime.h>
#include <cuda_bf16.h>
#include <math.h>
#include <stdint.h>

#define BATCH 4096
#define DIM   1024
#define LN_EPS 1e-5f

// ---------------- GEMM tiling ----------------
#define BM 128
#define BN 128
#define BK 32
#define NSTG 4
#define ROW_HALFS 40                    // 32 data + 8 pad halves (80 B row stride)
#define A_BYTES (BM * ROW_HALFS * 2)    // 10240
#define B_BYTES (BN * ROW_HALFS * 2)    // 10240
#define STG_BYTES (A_BYTES + B_BYTES)   // 20480
#define SMEM_TOTAL (NSTG * STG_BYTES)   // 81920

// ---------------- scratch (static device globals) ----------------
__device__ __align__(256) __nv_bfloat16 g_xhi [(size_t)BATCH * DIM];
__device__ __align__(256) __nv_bfloat16 g_xlo [(size_t)BATCH * DIM];
__device__ __align__(256) __nv_bfloat16 g_wqhi[(size_t)DIM * DIM];
__device__ __align__(256) __nv_bfloat16 g_wqlo[(size_t)DIM * DIM];
__device__ __align__(256) __nv_bfloat16 g_wkhi[(size_t)DIM * DIM];
__device__ __align__(256) __nv_bfloat16 g_wklo[(size_t)DIM * DIM];
__device__ __align__(256) __nv_bfloat16 g_wvhi[(size_t)DIM * DIM];
__device__ __align__(256) __nv_bfloat16 g_wvlo[(size_t)DIM * DIM];
__device__ __align__(256) __nv_bfloat16 g_fwhi[(size_t)DIM * DIM];
__device__ __align__(256) __nv_bfloat16 g_fwlo[(size_t)DIM * DIM];
__device__ __align__(256) __nv_bfloat16 g_qhi [(size_t)BATCH * DIM];
__device__ __align__(256) __nv_bfloat16 g_qlo [(size_t)BATCH * DIM];
__device__ __align__(256) __nv_bfloat16 g_khi [(size_t)BATCH * DIM];
__device__ __align__(256) __nv_bfloat16 g_klo [(size_t)BATCH * DIM];
__device__ __align__(256) __nv_bfloat16 g_vthi[(size_t)DIM * BATCH];   // V^T [DIM, BATCH]
__device__ __align__(256) __nv_bfloat16 g_vtlo[(size_t)DIM * BATCH];
__device__ __align__(256) float         g_s   [(size_t)BATCH * BATCH]; // scores fp32
__device__ __align__(256) __nv_bfloat16 g_phi [(size_t)BATCH * BATCH]; // attn hi
__device__ __align__(256) __nv_bfloat16 g_plo [(size_t)BATCH * BATCH]; // attn lo
__device__ __align__(256) __nv_bfloat16 g_avhi[(size_t)BATCH * DIM];
__device__ __align__(256) __nv_bfloat16 g_avlo[(size_t)BATCH * DIM];
__device__ __align__(256) float         g_h   [(size_t)BATCH * DIM];

// ---------------- PTX helpers ----------------
__device__ __forceinline__ uint32_t smem_u32(const void* p) {
    uint32_t a;
    asm("{ .reg .u64 t; cvta.to.shared.u64 t, %1; cvt.u32.u64 %0, t; }" : "=r"(a) : "l"(p));
    return a;
}

#define CP_ASYNC16(dst, src) \
    asm volatile("cp.async.cg.shared.global [%0], [%1], 16;" :: "r"(dst), "l"(src) : "memory")
#define CP_COMMIT() asm volatile("cp.async.commit_group;" ::: "memory")
#define CP_WAIT()   asm volatile("cp.async.wait_group %0;" :: "n"(NSTG - 2) : "memory")

__device__ __forceinline__ void ldm4(uint32_t& r0, uint32_t& r1, uint32_t& r2, uint32_t& r3,
                                     uint32_t addr) {
    asm volatile("ldmatrix.sync.aligned.m8n8.x4.shared.b16 {%0,%1,%2,%3}, [%4];"
                 : "=r"(r0), "=r"(r1), "=r"(r2), "=r"(r3) : "r"(addr));
}

__device__ __forceinline__ void mma16816(float& c0, float& c1, float& c2, float& c3,
                                         uint32_t a0, uint32_t a1, uint32_t a2, uint32_t a3,
                                         uint32_t b0, uint32_t b1) {
    asm volatile("mma.sync.aligned.m16n8k16.row.col.f32.bf16.bf16.f32 "
                 "{%0,%1,%2,%3}, {%4,%5,%6,%7}, {%8,%9}, {%0,%1,%2,%3};"
                 : "+f"(c0), "+f"(c1), "+f"(c2), "+f"(c3)
                 : "r"(a0), "r"(a1), "r"(a2), "r"(a3), "r"(b0), "r"(b1));
}

// stage loader: A tile 128x32 bf16 + B tile 128x32 bf16, padded rows (80B stride)
__device__ __forceinline__ void load_stage(
    uint32_t sbase, int tid,
    const __nv_bfloat16* __restrict__ A, const __nv_bfloat16* __restrict__ B, int K)
{
    #pragma unroll
    for (int i = 0; i < 4; i++) {
        int c   = tid + i * 256;          // 0..1023 chunk id (16B chunks)
        int cc  = c & 511;
        int row = cc >> 2;
        int col = cc & 3;
        const __nv_bfloat16* src = (c < 512 ? A : B) + (size_t)row * K + col * 8;
        uint32_t dst = sbase + (c < 512 ? 0 : A_BYTES) + row * (ROW_HALFS * 2) + col * 16;
        CP_ASYNC16(dst, src);
    }
}

// ---------------- HMMA split-bf16 GEMM ----------------
// C[M,N] = (Ahi+Alo)[M,K] x (Bhi+Blo)[N,K]^T  (NT; lo*lo dropped)
// MODE 0: write Chi/Clo bf16        MODE 1: Chi/Clo transposed (ld = Mtot)
// MODE 2: Cf fp32 scaled by alpha   MODE 3: Cf = acc + bias[col] + resid
template<int MODE>
__global__ __launch_bounds__(256) void gemm_mma(
    const __nv_bfloat16* __restrict__ Ahi, const __nv_bfloat16* __restrict__ Alo,
    const __nv_bfloat16* __restrict__ Bhi, const __nv_bfloat16* __restrict__ Blo,
    int K, int N, int Mtot, float alpha,
    float* __restrict__ Cf,
    __nv_bfloat16* __restrict__ Chi, __nv_bfloat16* __restrict__ Clo,
    const float* __restrict__ bias, const float* __restrict__ resid)
{
    extern __shared__ __align__(16) char smem_raw[];
    const uint32_t sb = smem_u32(smem_raw);

    const int tid = threadIdx.x;
    const int wid = tid >> 5;
    const int lid = tid & 31;
    const int warp_m = wid >> 2;          // 0..1  -> 64-row block
    const int warp_n = wid & 3;           // 0..3  -> 32-col block

    const int KC = K / BK;
    const int T  = 3 * KC;
    const __nv_bfloat16* Ap[3] = {Ahi, Ahi, Alo};
    const __nv_bfloat16* Bp[3] = {Bhi, Blo, Bhi};
    const size_t arow = (size_t)blockIdx.y * BM * K;
    const size_t brow = (size_t)blockIdx.x * BN * K;

    float acc[4][4][4];
    #pragma unroll
    for (int i = 0; i < 4; i++)
        #pragma unroll
        for (int j = 0; j < 4; j++)
            #pragma unroll
            for (int e = 0; e < 4; e++) acc[i][j][e] = 0.f;

    // per-lane ldmatrix address components
    const int a_r  = lid & 15;            // row within 16-row m tile
    const int a_k8 = (lid >> 4) & 1;      // k 8-half group
    const int b_r  = lid & 7;             // row (n) within 8
    const int b_t  = (lid >> 4) & 1;      // which n-tile of the x4 pair
    const int b_k8 = (lid >> 3) & 1;      // k 8-half group

    // prologue
    #pragma unroll
    for (int u = 0; u < NSTG - 1; u++) {
        int p = u / KC, kc = u - p * KC;
        load_stage(sb + u * STG_BYTES, tid, Ap[p] + arow + kc * BK, Bp[p] + brow + kc * BK, K);
        CP_COMMIT();
    }

    for (int t = 0; t < T; t++) {
        CP_WAIT();
        __syncthreads();

        // issue next stage loads (slot (t-1)%NSTG; safe: all warps past compute t-1)
        const int u = t + NSTG - 1;
        if (u < T) {
            const int su = u & (NSTG - 1);
            int p = u / KC, kc = u - p * KC;
            load_stage(sb + su * STG_BYTES, tid, Ap[p] + arow + kc * BK, Bp[p] + brow + kc * BK, K);
        }
        CP_COMMIT();

        // compute stage t
        const uint32_t aB = sb + (t & (NSTG - 1)) * STG_BYTES;
        const uint32_t bB = aB + A_BYTES;
        #pragma unroll
        for (int ks = 0; ks < 2; ks++) {
            uint32_t a[4][4];
            #pragma unroll
            for (int mi = 0; mi < 4; mi++) {
                uint32_t addr = aB +
                    ((warp_m * 64 + mi * 16 + a_r) * ROW_HALFS + ks * 16 + a_k8 * 8) * 2;
                ldm4(a[mi][0], a[mi][1], a[mi][2], a[mi][3], addr);
            }
            uint32_t b[4][2];
            #pragma unroll
            for (int j = 0; j < 2; j++) {
                uint32_t addr = bB +
                    ((warp_n * 32 + (2 * j + b_t) * 8 + b_r) * ROW_HALFS + ks * 16 + b_k8 * 8) * 2;
                ldm4(b[2 * j][0], b[2 * j][1], b[2 * j + 1][0], b[2 * j + 1][1], addr);
            }
            #pragma unroll
            for (int mi = 0; mi < 4; mi++)
                #pragma unroll
                for (int ni = 0; ni < 4; ni++)
                    mma16816(acc[mi][ni][0], acc[mi][ni][1], acc[mi][ni][2], acc[mi][ni][3],
                             a[mi][0], a[mi][1], a[mi][2], a[mi][3],
                             b[ni][0], b[ni][1]);
        }
    }

    // ---------------- epilogue ----------------
    const int qr = lid >> 2;              // 0..7
    const int qc = (lid & 3) * 2;         // 0,2,4,6
    #pragma unroll
    for (int mi = 0; mi < 4; mi++) {
        #pragma unroll
        for (int half = 0; half < 2; half++) {
            const int r = blockIdx.y * BM + warp_m * 64 + mi * 16 + qr + half * 8;
            #pragma unroll
            for (int ni = 0; ni < 4; ni++) {
                const int c = blockIdx.x * BN + warp_n * 32 + ni * 8 + qc;
                float f0 = acc[mi][ni][half * 2 + 0];
                float f1 = acc[mi][ni][half * 2 + 1];
                if (MODE == 2) {
                    float2 o = {f0 * alpha, f1 * alpha};
                    *reinterpret_cast<float2*>(Cf + (size_t)r * N + c) = o;
                } else if (MODE == 3) {
                    const float2 b2 = *reinterpret_cast<const float2*>(bias + c);
                    const float2 x2 = *reinterpret_cast<const float2*>(resid + (size_t)r * N + c);
                    float2 o = {f0 + b2.x + x2.x, f1 + b2.y + x2.y};
                    *reinterpret_cast<float2*>(Cf + (size_t)r * N + c) = o;
                } else if (MODE == 0) {
                    __nv_bfloat16 h0 = __float2bfloat16_rn(f0);
                    __nv_bfloat16 h1 = __float2bfloat16_rn(f1);
                    float l0 = f0 - __bfloat162float(h0);
                    float l1 = f1 - __bfloat162float(h1);
                    *reinterpret_cast<__nv_bfloat162*>(Chi + (size_t)r * N + c) =
                        __halves2bfloat162(h0, h1);
                    *reinterpret_cast<__nv_bfloat162*>(Clo + (size_t)r * N + c) =
                        __halves2bfloat162(__float2bfloat16_rn(l0), __float2bfloat16_rn(l1));
                } else { // MODE 1: transposed split write (produces V^T)
                    __nv_bfloat16 h0 = __float2bfloat16_rn(f0);
                    __nv_bfloat16 h1 = __float2bfloat16_rn(f1);
                    Chi[(size_t)(c + 0) * Mtot + r] = h0;
                    Chi[(size_t)(c + 1) * Mtot + r] = h1;
                    Clo[(size_t)(c + 0) * Mtot + r] = __float2bfloat16_rn(f0 - __bfloat162float(h0));
                    Clo[(size_t)(c + 1) * Mtot + r] = __float2bfloat16_rn(f1 - __bfloat162float(h1));
                }
            }
        }
    }
}

// ---------------- fp32 -> bf16 hi/lo split ----------------
__global__ __launch_bounds__(256) void split_f32(
    const float* __restrict__ src, __nv_bfloat16* __restrict__ hi,
    __nv_bfloat16* __restrict__ lo, int n4)
{
    int i = blockIdx.x * 256 + threadIdx.x;
    if (i >= n4) return;
    float4 v = reinterpret_cast<const float4*>(src)[i];
    __nv_bfloat16 h0 = __float2bfloat16_rn(v.x), h1 = __float2bfloat16_rn(v.y);
    __nv_bfloat16 h2 = __float2bfloat16_rn(v.z), h3 = __float2bfloat16_rn(v.w);
    float l0 = v.x - __bfloat162float(h0), l1 = v.y - __bfloat162float(h1);
    float l2 = v.z - __bfloat162float(h2), l3 = v.w - __bfloat162float(h3);
    reinterpret_cast<__nv_bfloat162*>(hi)[i * 2 + 0] = __halves2bfloat162(h0, h1);
    reinterpret_cast<__nv_bfloat162*>(hi)[i * 2 + 1] = __halves2bfloat162(h2, h3);
    reinterpret_cast<__nv_bfloat162*>(lo)[i * 2 + 0] =
        __halves2bfloat162(__float2bfloat16_rn(l0), __float2bfloat16_rn(l1));
    reinterpret_cast<__nv_bfloat162*>(lo)[i * 2 + 1] =
        __halves2bfloat162(__float2bfloat16_rn(l2), __float2bfloat16_rn(l3));
}

// ---------------- row softmax: fp32 scores -> bf16 hi/lo probs ----------------
__global__ __launch_bounds__(256) void softmax_split(
    const float* __restrict__ S, __nv_bfloat16* __restrict__ Phi,
    __nv_bfloat16* __restrict__ Plo)
{
    __shared__ float red[8];
    const int tid = threadIdx.x;
    const float* p = S + (size_t)blockIdx.x * BATCH;

    float4 v[4];
    float m = -1e30f;
    #pragma unroll
    for (int i = 0; i < 4; i++) {
        v[i] = *reinterpret_cast<const float4*>(p + (size_t)(i * 256 + tid) * 4);
        m = fmaxf(m, fmaxf(fmaxf(v[i].x, v[i].y), fmaxf(v[i].z, v[i].w)));
    }
    #pragma unroll
    for (int o = 16; o; o >>= 1) m = fmaxf(m, __shfl_xor_sync(0xffffffffu, m, o));
    if ((tid & 31) == 0) red[tid >> 5] = m;
    __syncthreads();
    m = red[0];
    #pragma unroll
    for (int i = 1; i < 8; i++) m = fmaxf(m, red[i]);
    __syncthreads();

    float s = 0.f;
    #pragma unroll
    for (int i = 0; i < 4; i++) {
        v[i].x = __expf(v[i].x - m); v[i].y = __expf(v[i].y - m);
        v[i].z = __expf(v[i].z - m); v[i].w = __expf(v[i].w - m);
        s += v[i].x + v[i].y + v[i].z + v[i].w;
    }
    #pragma unroll
    for (int o = 16; o; o >>= 1) s += __shfl_xor_sync(0xffffffffu, s, o);
    if ((tid & 31) == 0) red[tid >> 5] = s;
    __syncthreads();
    s = red[0];
    #pragma unroll
    for (int i = 1; i < 8; i++) s += red[i];
    const float rinv = 1.f / s;

    __nv_bfloat16* phr = Phi + (size_t)blockIdx.x * BATCH;
    __nv_bfloat16* plr = Plo + (size_t)blockIdx.x * BATCH;
    #pragma unroll
    for (int i = 0; i < 4; i++) {
        const int e0 = (i * 256 + tid) * 4;
        float f[4] = {v[i].x * rinv, v[i].y * rinv, v[i].z * rinv, v[i].w * rinv};
        __nv_bfloat16 h[4];
        float l[4];
        #pragma unroll
        for (int j = 0; j < 4; j++) {
            h[j] = __float2bfloat16_rn(f[j]);
            l[j] = f[j] - __bfloat162float(h[j]);
        }
        reinterpret_cast<__nv_bfloat162*>(phr + e0)[0] = __halves2bfloat162(h[0], h[1]);
        reinterpret_cast<__nv_bfloat162*>(phr + e0)[1] = __halves2bfloat162(h[2], h[3]);
        reinterpret_cast<__nv_bfloat162*>(plr + e0)[0] =
            __halves2bfloat162(__float2bfloat16_rn(l[0]), __float2bfloat16_rn(l[1]));
        reinterpret_cast<__nv_bfloat162*>(plr + e0)[1] =
            __halves2bfloat162(__float2bfloat16_rn(l[2]), __float2bfloat16_rn(l[3]));
    }
}

// ---------------- layernorm ----------------
__global__ __launch_bounds__(256) void layernorm_rows(
    const float* __restrict__ H, const float* __restrict__ gamma,
    const float* __restrict__ beta, float* __restrict__ out)
{
    __shared__ float redS[8], redQ[8];
    const int tid = threadIdx.x;
    const float* p = H + (size_t)blockIdx.x * DIM;

    float4 v = *reinterpret_cast<const float4*>(p + tid * 4);
    float s  = v.x + v.y + v.z + v.w;
    float ss = v.x * v.x + v.y * v.y + v.z * v.z + v.w * v.w;
    #pragma unroll
    for (int o = 16; o; o >>= 1) {
        s  += __shfl_xor_sync(0xffffffffu, s, o);
        ss += __shfl_xor_sync(0xffffffffu, ss, o);
    }
    if ((tid & 31) == 0) { redS[tid >> 5] = s; redQ[tid >> 5] = ss; }
    __syncthreads();
    s = 0.f; ss = 0.f;
    #pragma unroll
    for (int i = 0; i < 8; i++) { s += redS[i]; ss += redQ[i]; }

    const float mu  = s * (1.f / DIM);
    const float var = ss * (1.f / DIM) - mu * mu;
    const float rs  = rsqrtf(var + LN_EPS);

    float4 g = *reinterpret_cast<const float4*>(gamma + tid * 4);
    float4 b = *reinterpret_cast<const float4*>(beta  + tid * 4);
    float4 o;
    o.x = (v.x - mu) * rs * g.x + b.x;
    o.y = (v.y - mu) * rs * g.y + b.y;
    o.z = (v.z - mu) * rs * g.z + b.z;
    o.w = (v.w - mu) * rs * g.w + b.w;
    *reinterpret_cast<float4*>(out + (size_t)blockIdx.x * DIM + tid * 4) = o;
}

// ---------------- launch ----------------
extern "C" void kernel_launch(void* const* d_in, const int* in_sizes, int n_in,
                              void* d_out, int out_size)
{
    const float* x     = (const float*)d_in[0];
    const float* Wq    = (const float*)d_in[1];
    const float* Wk    = (const float*)d_in[2];
    const float* Wv    = (const float*)d_in[3];
    const float* fcw   = (const float*)d_in[4];
    const float* fcb   = (const float*)d_in[5];
    const float* gamma = (const float*)d_in[6];
    const float* beta  = (const float*)d_in[7];
    float* out = (float*)d_out;

    __nv_bfloat16 *xhi, *xlo, *wqhi, *wqlo, *wkhi, *wklo, *wvhi, *wvlo, *fwhi, *fwlo;
    __nv_bfloat16 *qhi, *qlo, *khi, *klo, *vthi, *vtlo, *phi, *plo, *avhi, *avlo;
    float *sc, *h;
    cudaGetSymbolAddress((void**)&xhi,  g_xhi);  cudaGetSymbolAddress((void**)&xlo,  g_xlo);
    cudaGetSymbolAddress((void**)&wqhi, g_wqhi); cudaGetSymbolAddress((void**)&wqlo, g_wqlo);
    cudaGetSymbolAddress((void**)&wkhi, g_wkhi); cudaGetSymbolAddress((void**)&wklo, g_wklo);
    cudaGetSymbolAddress((void**)&wvhi, g_wvhi); cudaGetSymbolAddress((void**)&wvlo, g_wvlo);
    cudaGetSymbolAddress((void**)&fwhi, g_fwhi); cudaGetSymbolAddress((void**)&fwlo, g_fwlo);
    cudaGetSymbolAddress((void**)&qhi,  g_qhi);  cudaGetSymbolAddress((void**)&qlo,  g_qlo);
    cudaGetSymbolAddress((void**)&khi,  g_khi);  cudaGetSymbolAddress((void**)&klo,  g_klo);
    cudaGetSymbolAddress((void**)&vthi, g_vthi); cudaGetSymbolAddress((void**)&vtlo, g_vtlo);
    cudaGetSymbolAddress((void**)&phi,  g_phi);  cudaGetSymbolAddress((void**)&plo,  g_plo);
    cudaGetSymbolAddress((void**)&avhi, g_avhi); cudaGetSymbolAddress((void**)&avlo, g_avlo);
    cudaGetSymbolAddress((void**)&sc,   g_s);    cudaGetSymbolAddress((void**)&h,    g_h);

    cudaFuncSetAttribute(gemm_mma<0>, cudaFuncAttributeMaxDynamicSharedMemorySize, SMEM_TOTAL);
    cudaFuncSetAttribute(gemm_mma<1>, cudaFuncAttributeMaxDynamicSharedMemorySize, SMEM_TOTAL);
    cudaFuncSetAttribute(gemm_mma<2>, cudaFuncAttributeMaxDynamicSharedMemorySize, SMEM_TOTAL);
    cudaFuncSetAttribute(gemm_mma<3>, cudaFuncAttributeMaxDynamicSharedMemorySize, SMEM_TOTAL);

    // split inputs into bf16 hi/lo
    const int nX = BATCH * DIM / 4, nW = DIM * DIM / 4;
    split_f32<<<(nX + 255) / 256, 256>>>(x,   xhi,  xlo,  nX);
    split_f32<<<(nW + 255) / 256, 256>>>(Wq,  wqhi, wqlo, nW);
    split_f32<<<(nW + 255) / 256, 256>>>(Wk,  wkhi, wklo, nW);
    split_f32<<<(nW + 255) / 256, 256>>>(Wv,  wvhi, wvlo, nW);
    split_f32<<<(nW + 255) / 256, 256>>>(fcw, fwhi, fwlo, nW);

    const dim3 blk(256);
    const dim3 gP(DIM / BN,   BATCH / BM);   // 8 x 32
    const dim3 gS(BATCH / BN, BATCH / BM);   // 32 x 32

    // q = x@Wq^T, k = x@Wk^T (split out); v = x@Wv^T (split, transposed out)
    gemm_mma<0><<<gP, blk, SMEM_TOTAL>>>(xhi, xlo, wqhi, wqlo, DIM, DIM, BATCH, 1.f,
                                         nullptr, qhi, qlo, nullptr, nullptr);
    gemm_mma<0><<<gP, blk, SMEM_TOTAL>>>(xhi, xlo, wkhi, wklo, DIM, DIM, BATCH, 1.f,
                                         nullptr, khi, klo, nullptr, nullptr);
    gemm_mma<1><<<gP, blk, SMEM_TOTAL>>>(xhi, xlo, wvhi, wvlo, DIM, DIM, BATCH, 1.f,
                                         nullptr, vthi, vtlo, nullptr, nullptr);

    // scores = (k @ q^T) / 32  (fp32 out)
    gemm_mma<2><<<gS, blk, SMEM_TOTAL>>>(khi, klo, qhi, qlo, DIM, BATCH, BATCH, 0.03125f,
                                         sc, nullptr, nullptr, nullptr, nullptr);

    // softmax -> attn hi/lo
    softmax_split<<<BATCH, 256>>>(sc, phi, plo);

    // av = attn @ v  (B = v^T, K = 4096)
    gemm_mma<0><<<gP, blk, SMEM_TOTAL>>>(phi, plo, vthi, vtlo, BATCH, DIM, BATCH, 1.f,
                                         nullptr, avhi, avlo, nullptr, nullptr);

    // h = av @ fcw^T + fcb + x  (fp32 out)
    gemm_mma<3><<<gP, blk, SMEM_TOTAL>>>(avhi, avlo, fwhi, fwlo, DIM, DIM, BATCH, 1.f,
                                         h, nullptr, nullptr, fcb, x);

    // layernorm -> out
    layernorm_rows<<<BATCH, 256>>>(h, gamma, beta, out);
}

// round 4
// speedup vs baseline: 5.2590x; 2.0349x over previous
#include <cuda_runtime.h>
#include <cuda_bf16.h>
#include <math.h>
#include <stdint.h>

#define BATCH 4096
#define DIM   1024
#define LN_EPS 1e-5f

// ---------------- GEMM tiling ----------------
#define BM 128
#define BN 128
#define BK 32
#define NSTG 4
#define ROW_HALFS 40                    // 32 data + 8 pad halves (80 B row stride)
#define A_BYTES (BM * ROW_HALFS * 2)    // 10240
#define B_BYTES (BN * ROW_HALFS * 2)    // 10240
#define STG_BYTES (A_BYTES + B_BYTES)   // 20480
#define SMEM_TOTAL (NSTG * STG_BYTES)   // 81920

// ---------------- scratch (static device globals) ----------------
__device__ __align__(256) __nv_bfloat16 g_xhi [(size_t)BATCH * DIM];
__device__ __align__(256) __nv_bfloat16 g_wqhi[(size_t)DIM * DIM];
__device__ __align__(256) __nv_bfloat16 g_wkhi[(size_t)DIM * DIM];
__device__ __align__(256) __nv_bfloat16 g_wvhi[(size_t)DIM * DIM];
__device__ __align__(256) __nv_bfloat16 g_fwhi[(size_t)DIM * DIM];
__device__ __align__(256) __nv_bfloat16 g_qhi [(size_t)BATCH * DIM];
__device__ __align__(256) __nv_bfloat16 g_khi [(size_t)BATCH * DIM];
__device__ __align__(256) __nv_bfloat16 g_klo [(size_t)BATCH * DIM];
__device__ __align__(256) __nv_bfloat16 g_vthi[(size_t)DIM * BATCH];   // V^T [DIM, BATCH]
__device__ __align__(256) float         g_s   [(size_t)BATCH * BATCH]; // scores fp32
__device__ __align__(256) __nv_bfloat16 g_phi [(size_t)BATCH * BATCH]; // attn probs bf16
__device__ __align__(256) __nv_bfloat16 g_avhi[(size_t)BATCH * DIM];
__device__ __align__(256) float         g_h   [(size_t)BATCH * DIM];

// ---------------- PTX helpers ----------------
__device__ __forceinline__ uint32_t smem_u32(const void* p) {
    uint32_t a;
    asm("{ .reg .u64 t; cvta.to.shared.u64 t, %1; cvt.u32.u64 %0, t; }" : "=r"(a) : "l"(p));
    return a;
}

#define CP_ASYNC16(dst, src) \
    asm volatile("cp.async.cg.shared.global [%0], [%1], 16;" :: "r"(dst), "l"(src) : "memory")
#define CP_COMMIT() asm volatile("cp.async.commit_group;" ::: "memory")
#define CP_WAIT()   asm volatile("cp.async.wait_group %0;" :: "n"(NSTG - 2) : "memory")

__device__ __forceinline__ void ldm4(uint32_t& r0, uint32_t& r1, uint32_t& r2, uint32_t& r3,
                                     uint32_t addr) {
    asm volatile("ldmatrix.sync.aligned.m8n8.x4.shared.b16 {%0,%1,%2,%3}, [%4];"
                 : "=r"(r0), "=r"(r1), "=r"(r2), "=r"(r3) : "r"(addr));
}

__device__ __forceinline__ void mma16816(float& c0, float& c1, float& c2, float& c3,
                                         uint32_t a0, uint32_t a1, uint32_t a2, uint32_t a3,
                                         uint32_t b0, uint32_t b1) {
    asm volatile("mma.sync.aligned.m16n8k16.row.col.f32.bf16.bf16.f32 "
                 "{%0,%1,%2,%3}, {%4,%5,%6,%7}, {%8,%9}, {%0,%1,%2,%3};"
                 : "+f"(c0), "+f"(c1), "+f"(c2), "+f"(c3)
                 : "r"(a0), "r"(a1), "r"(a2), "r"(a3), "r"(b0), "r"(b1));
}

// stage loader: A tile 128x32 bf16 + B tile 128x32 bf16, padded rows (80B stride)
__device__ __forceinline__ void load_stage(
    uint32_t sbase, int tid,
    const __nv_bfloat16* __restrict__ A, const __nv_bfloat16* __restrict__ B, int K)
{
    #pragma unroll
    for (int i = 0; i < 4; i++) {
        int c   = tid + i * 256;          // 0..1023 chunk id (16B chunks)
        int cc  = c & 511;
        int row = cc >> 2;
        int col = cc & 3;
        const __nv_bfloat16* src = (c < 512 ? A : B) + (size_t)row * K + col * 8;
        uint32_t dst = sbase + (c < 512 ? 0 : A_BYTES) + row * (ROW_HALFS * 2) + col * 16;
        CP_ASYNC16(dst, src);
    }
}

// ---------------- HMMA GEMM, selectable precision passes --------------------
// C[M,N] = sum over passes of Ap[p][M,K] x Bp[p][N,K]^T  (all NT)
// PASSES 1: Ahi x Bhi
// PASSES 2: Ahi x Bhi + Alo x Bhi          (A split, B hi-only)
// MODE 0: write Chi/Clo bf16 split          MODE 2: Cf fp32 scaled by alpha
// MODE 3: Cf = acc + bias[col] + resid      MODE 4: Chi bf16 plain
// MODE 5: Chi bf16 plain transposed (ld = Mtot)
template<int MODE, int PASSES>
__global__ __launch_bounds__(256) void gemm_mma(
    const __nv_bfloat16* __restrict__ Ahi, const __nv_bfloat16* __restrict__ Alo,
    const __nv_bfloat16* __restrict__ Bhi,
    int K, int N, int Mtot, float alpha,
    float* __restrict__ Cf,
    __nv_bfloat16* __restrict__ Chi, __nv_bfloat16* __restrict__ Clo,
    const float* __restrict__ bias, const float* __restrict__ resid)
{
    extern __shared__ __align__(16) char smem_raw[];
    const uint32_t sb = smem_u32(smem_raw);

    const int tid = threadIdx.x;
    const int wid = tid >> 5;
    const int lid = tid & 31;
    const int warp_m = wid >> 2;          // 0..1  -> 64-row block
    const int warp_n = wid & 3;           // 0..3  -> 32-col block

    const int KC = K / BK;
    const int T  = PASSES * KC;
    const __nv_bfloat16* Ap[2] = {Ahi, Alo};
    const size_t arow = (size_t)blockIdx.y * BM * K;
    const size_t brow = (size_t)blockIdx.x * BN * K;

    float acc[4][4][4];
    #pragma unroll
    for (int i = 0; i < 4; i++)
        #pragma unroll
        for (int j = 0; j < 4; j++)
            #pragma unroll
            for (int e = 0; e < 4; e++) acc[i][j][e] = 0.f;

    const int a_r  = lid & 15;
    const int a_k8 = (lid >> 4) & 1;
    const int b_r  = lid & 7;
    const int b_t  = (lid >> 4) & 1;
    const int b_k8 = (lid >> 3) & 1;

    // prologue
    #pragma unroll
    for (int u = 0; u < NSTG - 1; u++) {
        int p = u / KC, kc = u - p * KC;
        load_stage(sb + u * STG_BYTES, tid, Ap[p] + arow + kc * BK, Bhi + brow + kc * BK, K);
        CP_COMMIT();
    }

    for (int t = 0; t < T; t++) {
        CP_WAIT();
        __syncthreads();

        const int u = t + NSTG - 1;
        if (u < T) {
            const int su = u & (NSTG - 1);
            int p = u / KC, kc = u - p * KC;
            load_stage(sb + su * STG_BYTES, tid, Ap[p] + arow + kc * BK, Bhi + brow + kc * BK, K);
        }
        CP_COMMIT();

        const uint32_t aB = sb + (t & (NSTG - 1)) * STG_BYTES;
        const uint32_t bB = aB + A_BYTES;
        #pragma unroll
        for (int ks = 0; ks < 2; ks++) {
            uint32_t a[4][4];
            #pragma unroll
            for (int mi = 0; mi < 4; mi++) {
                uint32_t addr = aB +
                    ((warp_m * 64 + mi * 16 + a_r) * ROW_HALFS + ks * 16 + a_k8 * 8) * 2;
                ldm4(a[mi][0], a[mi][1], a[mi][2], a[mi][3], addr);
            }
            uint32_t b[4][2];
            #pragma unroll
            for (int j = 0; j < 2; j++) {
                uint32_t addr = bB +
                    ((warp_n * 32 + (2 * j + b_t) * 8 + b_r) * ROW_HALFS + ks * 16 + b_k8 * 8) * 2;
                ldm4(b[2 * j][0], b[2 * j][1], b[2 * j + 1][0], b[2 * j + 1][1], addr);
            }
            #pragma unroll
            for (int mi = 0; mi < 4; mi++)
                #pragma unroll
                for (int ni = 0; ni < 4; ni++)
                    mma16816(acc[mi][ni][0], acc[mi][ni][1], acc[mi][ni][2], acc[mi][ni][3],
                             a[mi][0], a[mi][1], a[mi][2], a[mi][3],
                             b[ni][0], b[ni][1]);
        }
    }

    // ---------------- epilogue ----------------
    const int qr = lid >> 2;              // 0..7
    const int qc = (lid & 3) * 2;         // 0,2,4,6
    #pragma unroll
    for (int mi = 0; mi < 4; mi++) {
        #pragma unroll
        for (int half = 0; half < 2; half++) {
            const int r = blockIdx.y * BM + warp_m * 64 + mi * 16 + qr + half * 8;
            #pragma unroll
            for (int ni = 0; ni < 4; ni++) {
                const int c = blockIdx.x * BN + warp_n * 32 + ni * 8 + qc;
                float f0 = acc[mi][ni][half * 2 + 0];
                float f1 = acc[mi][ni][half * 2 + 1];
                if (MODE == 2) {
                    float2 o = {f0 * alpha, f1 * alpha};
                    *reinterpret_cast<float2*>(Cf + (size_t)r * N + c) = o;
                } else if (MODE == 3) {
                    const float2 b2 = *reinterpret_cast<const float2*>(bias + c);
                    const float2 x2 = *reinterpret_cast<const float2*>(resid + (size_t)r * N + c);
                    float2 o = {f0 + b2.x + x2.x, f1 + b2.y + x2.y};
                    *reinterpret_cast<float2*>(Cf + (size_t)r * N + c) = o;
                } else if (MODE == 0) {
                    __nv_bfloat16 h0 = __float2bfloat16_rn(f0);
                    __nv_bfloat16 h1 = __float2bfloat16_rn(f1);
                    float l0 = f0 - __bfloat162float(h0);
                    float l1 = f1 - __bfloat162float(h1);
                    *reinterpret_cast<__nv_bfloat162*>(Chi + (size_t)r * N + c) =
                        __halves2bfloat162(h0, h1);
                    *reinterpret_cast<__nv_bfloat162*>(Clo + (size_t)r * N + c) =
                        __halves2bfloat162(__float2bfloat16_rn(l0), __float2bfloat16_rn(l1));
                } else if (MODE == 4) {
                    *reinterpret_cast<__nv_bfloat162*>(Chi + (size_t)r * N + c) =
                        __halves2bfloat162(__float2bfloat16_rn(f0), __float2bfloat16_rn(f1));
                } else { // MODE 5: plain bf16 transposed write (produces V^T)
                    Chi[(size_t)(c + 0) * Mtot + r] = __float2bfloat16_rn(f0);
                    Chi[(size_t)(c + 1) * Mtot + r] = __float2bfloat16_rn(f1);
                }
            }
        }
    }
}

// ---------------- fp32 -> bf16 convert ----------------
__global__ __launch_bounds__(256) void cvt_bf16(
    const float* __restrict__ src, __nv_bfloat16* __restrict__ dst, int n4)
{
    int i = blockIdx.x * 256 + threadIdx.x;
    if (i >= n4) return;
    float4 v = reinterpret_cast<const float4*>(src)[i];
    reinterpret_cast<__nv_bfloat162*>(dst)[i * 2 + 0] =
        __halves2bfloat162(__float2bfloat16_rn(v.x), __float2bfloat16_rn(v.y));
    reinterpret_cast<__nv_bfloat162*>(dst)[i * 2 + 1] =
        __halves2bfloat162(__float2bfloat16_rn(v.z), __float2bfloat16_rn(v.w));
}

// ---------------- row softmax: fp32 scores -> bf16 probs ----------------
__global__ __launch_bounds__(256) void softmax_hi(
    const float* __restrict__ S, __nv_bfloat16* __restrict__ Phi)
{
    __shared__ float red[8];
    const int tid = threadIdx.x;
    const float* p = S + (size_t)blockIdx.x * BATCH;

    float4 v[4];
    float m = -1e30f;
    #pragma unroll
    for (int i = 0; i < 4; i++) {
        v[i] = *reinterpret_cast<const float4*>(p + (size_t)(i * 256 + tid) * 4);
        m = fmaxf(m, fmaxf(fmaxf(v[i].x, v[i].y), fmaxf(v[i].z, v[i].w)));
    }
    #pragma unroll
    for (int o = 16; o; o >>= 1) m = fmaxf(m, __shfl_xor_sync(0xffffffffu, m, o));
    if ((tid & 31) == 0) red[tid >> 5] = m;
    __syncthreads();
    m = red[0];
    #pragma unroll
    for (int i = 1; i < 8; i++) m = fmaxf(m, red[i]);
    __syncthreads();

    float s = 0.f;
    #pragma unroll
    for (int i = 0; i < 4; i++) {
        v[i].x = __expf(v[i].x - m); v[i].y = __expf(v[i].y - m);
        v[i].z = __expf(v[i].z - m); v[i].w = __expf(v[i].w - m);
        s += v[i].x + v[i].y + v[i].z + v[i].w;
    }
    #pragma unroll
    for (int o = 16; o; o >>= 1) s += __shfl_xor_sync(0xffffffffu, s, o);
    if ((tid & 31) == 0) red[tid >> 5] = s;
    __syncthreads();
    s = red[0];
    #pragma unroll
    for (int i = 1; i < 8; i++) s += red[i];
    const float rinv = 1.f / s;

    __nv_bfloat16* phr = Phi + (size_t)blockIdx.x * BATCH;
    #pragma unroll
    for (int i = 0; i < 4; i++) {
        const int e0 = (i * 256 + tid) * 4;
        reinterpret_cast<__nv_bfloat162*>(phr + e0)[0] = __halves2bfloat162(
            __float2bfloat16_rn(v[i].x * rinv), __float2bfloat16_rn(v[i].y * rinv));
        reinterpret_cast<__nv_bfloat162*>(phr + e0)[1] = __halves2bfloat162(
            __float2bfloat16_rn(v[i].z * rinv), __float2bfloat16_rn(v[i].w * rinv));
    }
}

// ---------------- layernorm ----------------
__global__ __launch_bounds__(256) void layernorm_rows(
    const float* __restrict__ H, const float* __restrict__ gamma,
    const float* __restrict__ beta, float* __restrict__ out)
{
    __shared__ float redS[8], redQ[8];
    const int tid = threadIdx.x;
    const float* p = H + (size_t)blockIdx.x * DIM;

    float4 v = *reinterpret_cast<const float4*>(p + tid * 4);
    float s  = v.x + v.y + v.z + v.w;
    float ss = v.x * v.x + v.y * v.y + v.z * v.z + v.w * v.w;
    #pragma unroll
    for (int o = 16; o; o >>= 1) {
        s  += __shfl_xor_sync(0xffffffffu, s, o);
        ss += __shfl_xor_sync(0xffffffffu, ss, o);
    }
    if ((tid & 31) == 0) { redS[tid >> 5] = s; redQ[tid >> 5] = ss; }
    __syncthreads();
    s = 0.f; ss = 0.f;
    #pragma unroll
    for (int i = 0; i < 8; i++) { s += redS[i]; ss += redQ[i]; }

    const float mu  = s * (1.f / DIM);
    const float var = ss * (1.f / DIM) - mu * mu;
    const float rs  = rsqrtf(var + LN_EPS);

    float4 g = *reinterpret_cast<const float4*>(gamma + tid * 4);
    float4 b = *reinterpret_cast<const float4*>(beta  + tid * 4);
    float4 o;
    o.x = (v.x - mu) * rs * g.x + b.x;
    o.y = (v.y - mu) * rs * g.y + b.y;
    o.z = (v.z - mu) * rs * g.z + b.z;
    o.w = (v.w - mu) * rs * g.w + b.w;
    *reinterpret_cast<float4*>(out + (size_t)blockIdx.x * DIM + tid * 4) = o;
}

// ---------------- launch ----------------
extern "C" void kernel_launch(void* const* d_in, const int* in_sizes, int n_in,
                              void* d_out, int out_size)
{
    const float* x     = (const float*)d_in[0];
    const float* Wq    = (const float*)d_in[1];
    const float* Wk    = (const float*)d_in[2];
    const float* Wv    = (const float*)d_in[3];
    const float* fcw   = (const float*)d_in[4];
    const float* fcb   = (const float*)d_in[5];
    const float* gamma = (const float*)d_in[6];
    const float* beta  = (const float*)d_in[7];
    float* out = (float*)d_out;

    __nv_bfloat16 *xhi, *wqhi, *wkhi, *wvhi, *fwhi;
    __nv_bfloat16 *qhi, *khi, *klo, *vthi, *phi, *avhi;
    float *sc, *h;
    cudaGetSymbolAddress((void**)&xhi,  g_xhi);
    cudaGetSymbolAddress((void**)&wqhi, g_wqhi);
    cudaGetSymbolAddress((void**)&wkhi, g_wkhi);
    cudaGetSymbolAddress((void**)&wvhi, g_wvhi);
    cudaGetSymbolAddress((void**)&fwhi, g_fwhi);
    cudaGetSymbolAddress((void**)&qhi,  g_qhi);
    cudaGetSymbolAddress((void**)&khi,  g_khi);
    cudaGetSymbolAddress((void**)&klo,  g_klo);
    cudaGetSymbolAddress((void**)&vthi, g_vthi);
    cudaGetSymbolAddress((void**)&phi,  g_phi);
    cudaGetSymbolAddress((void**)&avhi, g_avhi);
    cudaGetSymbolAddress((void**)&sc,   g_s);
    cudaGetSymbolAddress((void**)&h,    g_h);

    cudaFuncSetAttribute(gemm_mma<4,1>, cudaFuncAttributeMaxDynamicSharedMemorySize, SMEM_TOTAL);
    cudaFuncSetAttribute(gemm_mma<0,1>, cudaFuncAttributeMaxDynamicSharedMemorySize, SMEM_TOTAL);
    cudaFuncSetAttribute(gemm_mma<5,1>, cudaFuncAttributeMaxDynamicSharedMemorySize, SMEM_TOTAL);
    cudaFuncSetAttribute(gemm_mma<2,2>, cudaFuncAttributeMaxDynamicSharedMemorySize, SMEM_TOTAL);
    cudaFuncSetAttribute(gemm_mma<3,1>, cudaFuncAttributeMaxDynamicSharedMemorySize, SMEM_TOTAL);

    // convert inputs to bf16 (hi)
    const int nX = BATCH * DIM / 4, nW = DIM * DIM / 4;
    cvt_bf16<<<(nX + 255) / 256, 256>>>(x,   xhi,  nX);
    cvt_bf16<<<(nW + 255) / 256, 256>>>(Wq,  wqhi, nW);
    cvt_bf16<<<(nW + 255) / 256, 256>>>(Wk,  wkhi, nW);
    cvt_bf16<<<(nW + 255) / 256, 256>>>(Wv,  wvhi, nW);
    cvt_bf16<<<(nW + 255) / 256, 256>>>(fcw, fwhi, nW);

    const dim3 blk(256);
    const dim3 gP(DIM / BN,   BATCH / BM);   // 8 x 32
    const dim3 gS(BATCH / BN, BATCH / BM);   // 32 x 32

    // q = x@Wq^T (bf16 out); k = x@Wk^T (bf16 hi/lo out); v = x@Wv^T (bf16, transposed)
    gemm_mma<4,1><<<gP, blk, SMEM_TOTAL>>>(xhi, nullptr, wqhi, DIM, DIM, BATCH, 1.f,
                                           nullptr, qhi, nullptr, nullptr, nullptr);
    gemm_mma<0,1><<<gP, blk, SMEM_TOTAL>>>(xhi, nullptr, wkhi, DIM, DIM, BATCH, 1.f,
                                           nullptr, khi, klo, nullptr, nullptr);
    gemm_mma<5,1><<<gP, blk, SMEM_TOTAL>>>(xhi, nullptr, wvhi, DIM, DIM, BATCH, 1.f,
                                           nullptr, vthi, nullptr, nullptr, nullptr);

    // scores = ((khi + klo) @ qhi^T) / 32   (2-pass, fp32 out)
    gemm_mma<2,2><<<gS, blk, SMEM_TOTAL>>>(khi, klo, qhi, DIM, BATCH, BATCH, 0.03125f,
                                           sc, nullptr, nullptr, nullptr, nullptr);

    // softmax -> probs bf16
    softmax_hi<<<BATCH, 256>>>(sc, phi);

    // av = attn @ v  (B = v^T, K = 4096, bf16 out)
    gemm_mma<4,1><<<gP, blk, SMEM_TOTAL>>>(phi, nullptr, vthi, BATCH, DIM, BATCH, 1.f,
                                           nullptr, avhi, nullptr, nullptr, nullptr);

    // h = av @ fcw^T + fcb + x  (fp32 out)
    gemm_mma<3,1><<<gP, blk, SMEM_TOTAL>>>(avhi, nullptr, fwhi, DIM, DIM, BATCH, 1.f,
                                           h, nullptr, nullptr, fcb, x);

    // layernorm -> out
    layernorm_rows<<<BATCH, 256>>>(h, gamma, beta, out);
}

// round 5
// speedup vs baseline: 7.3083x; 1.3897x over previous
#include <cuda_runtime.h>
#include <cuda_bf16.h>
#include <math.h>
#include <stdint.h>

#define BATCH 4096
#define DIM   1024
#define LN_EPS 1e-5f

// ---------------- GEMM tiling ----------------
#define BM 128
#define BN 128
#define BK 64
#define NSTG 3
#define ROW_HALFS 72                    // 64 data + 8 pad halves (144 B row stride)
#define A_BYTES (BM * ROW_HALFS * 2)    // 18432
#define B_BYTES (BN * ROW_HALFS * 2)    // 18432
#define STG_BYTES (A_BYTES + B_BYTES)   // 36864
#define SMEM_TOTAL (NSTG * STG_BYTES)   // 110592

// ---------------- scratch (static device globals) ----------------
__device__ __align__(256) __nv_bfloat16 g_xhi [(size_t)BATCH * DIM];
__device__ __align__(256) __nv_bfloat16 g_wqhi[(size_t)DIM * DIM];
__device__ __align__(256) __nv_bfloat16 g_wkhi[(size_t)DIM * DIM];
__device__ __align__(256) __nv_bfloat16 g_wvhi[(size_t)DIM * DIM];
__device__ __align__(256) __nv_bfloat16 g_fwhi[(size_t)DIM * DIM];
__device__ __align__(256) __nv_bfloat16 g_qhi [(size_t)BATCH * DIM];
__device__ __align__(256) __nv_bfloat16 g_khi [(size_t)BATCH * DIM];
__device__ __align__(256) __nv_bfloat16 g_vthi[(size_t)DIM * BATCH];   // V^T [DIM, BATCH]
__device__ __align__(256) float         g_s   [(size_t)BATCH * BATCH]; // scores fp32
__device__ __align__(256) __nv_bfloat16 g_phi [(size_t)BATCH * BATCH]; // attn probs bf16
__device__ __align__(256) __nv_bfloat16 g_avhi[(size_t)BATCH * DIM];
__device__ __align__(256) float         g_h   [(size_t)BATCH * DIM];

// ---------------- PTX helpers ----------------
__device__ __forceinline__ uint32_t smem_u32(const void* p) {
    uint32_t a;
    asm("{ .reg .u64 t; cvta.to.shared.u64 t, %1; cvt.u32.u64 %0, t; }" : "=r"(a) : "l"(p));
    return a;
}

#define CP_ASYNC16(dst, src) \
    asm volatile("cp.async.cg.shared.global [%0], [%1], 16;" :: "r"(dst), "l"(src) : "memory")
#define CP_COMMIT() asm volatile("cp.async.commit_group;" ::: "memory")
#define CP_WAIT()   asm volatile("cp.async.wait_group %0;" :: "n"(NSTG - 2) : "memory")

__device__ __forceinline__ void ldm4(uint32_t& r0, uint32_t& r1, uint32_t& r2, uint32_t& r3,
                                     uint32_t addr) {
    asm volatile("ldmatrix.sync.aligned.m8n8.x4.shared.b16 {%0,%1,%2,%3}, [%4];"
                 : "=r"(r0), "=r"(r1), "=r"(r2), "=r"(r3) : "r"(addr));
}

__device__ __forceinline__ void mma16816(float& c0, float& c1, float& c2, float& c3,
                                         uint32_t a0, uint32_t a1, uint32_t a2, uint32_t a3,
                                         uint32_t b0, uint32_t b1) {
    asm volatile("mma.sync.aligned.m16n8k16.row.col.f32.bf16.bf16.f32 "
                 "{%0,%1,%2,%3}, {%4,%5,%6,%7}, {%8,%9}, {%0,%1,%2,%3};"
                 : "+f"(c0), "+f"(c1), "+f"(c2), "+f"(c3)
                 : "r"(a0), "r"(a1), "r"(a2), "r"(a3), "r"(b0), "r"(b1));
}

// stage loader: A tile 128x64 bf16 + B tile 128x64 bf16, padded rows (144B stride)
__device__ __forceinline__ void load_stage(
    uint32_t sbase, int tid,
    const __nv_bfloat16* __restrict__ A, const __nv_bfloat16* __restrict__ B, int K)
{
    #pragma unroll
    for (int i = 0; i < 8; i++) {
        int c   = tid + i * 256;          // 0..2047 chunk id (16B chunks)
        int cc  = c & 1023;
        int row = cc >> 3;                // 0..127
        int col = cc & 7;                 // 0..7
        const __nv_bfloat16* src = (c < 1024 ? A : B) + (size_t)row * K + col * 8;
        uint32_t dst = sbase + (c < 1024 ? 0 : A_BYTES) + row * (ROW_HALFS * 2) + col * 16;
        CP_ASYNC16(dst, src);
    }
}

// ---------------- HMMA GEMM, selectable precision passes --------------------
// C[M,N] = sum over passes of Ap[p][M,K] x Bhi[N,K]^T  (all NT)
// PASSES 1: Ahi x Bhi      PASSES 2: Ahi x Bhi + Alo x Bhi
// MODE 2: Cf fp32 scaled by alpha      MODE 3: Cf = acc + bias[col] + resid
// MODE 4: Chi bf16 plain               MODE 5: Chi bf16 transposed (ld = Mtot)
template<int MODE, int PASSES>
__global__ __launch_bounds__(256) void gemm_mma(
    const __nv_bfloat16* __restrict__ Ahi, const __nv_bfloat16* __restrict__ Alo,
    const __nv_bfloat16* __restrict__ Bhi,
    int K, int N, int Mtot, float alpha,
    float* __restrict__ Cf, __nv_bfloat16* __restrict__ Chi,
    const float* __restrict__ bias, const float* __restrict__ resid)
{
    extern __shared__ __align__(16) char smem_raw[];
    const uint32_t sb = smem_u32(smem_raw);

    const int tid = threadIdx.x;
    const int wid = tid >> 5;
    const int lid = tid & 31;
    const int warp_m = wid >> 2;          // 0..1  -> 64-row block
    const int warp_n = wid & 3;           // 0..3  -> 32-col block

    const int KC = K / BK;
    const int T  = PASSES * KC;
    const __nv_bfloat16* Ap[2] = {Ahi, Alo};
    const size_t arow = (size_t)blockIdx.y * BM * K;
    const size_t brow = (size_t)blockIdx.x * BN * K;

    float acc[4][4][4];
    #pragma unroll
    for (int i = 0; i < 4; i++)
        #pragma unroll
        for (int j = 0; j < 4; j++)
            #pragma unroll
            for (int e = 0; e < 4; e++) acc[i][j][e] = 0.f;

    const int a_r  = lid & 15;
    const int a_k8 = (lid >> 4) & 1;
    const int b_r  = lid & 7;
    const int b_t  = (lid >> 4) & 1;
    const int b_k8 = (lid >> 3) & 1;

    // prologue: fill NSTG-1 stages
    #pragma unroll
    for (int u = 0; u < NSTG - 1; u++) {
        int p = u / KC, kc = u - p * KC;
        load_stage(sb + u * STG_BYTES, tid, Ap[p] + arow + kc * BK, Bhi + brow + kc * BK, K);
        CP_COMMIT();
    }

    for (int t = 0; t < T; t++) {
        CP_WAIT();
        __syncthreads();

        const int u = t + NSTG - 1;
        if (u < T) {
            int su = u % NSTG;
            int p = u / KC, kc = u - p * KC;
            load_stage(sb + su * STG_BYTES, tid, Ap[p] + arow + kc * BK, Bhi + brow + kc * BK, K);
        }
        CP_COMMIT();

        const uint32_t aB = sb + (t % NSTG) * STG_BYTES;
        const uint32_t bB = aB + A_BYTES;
        #pragma unroll
        for (int ks = 0; ks < 4; ks++) {
            uint32_t a[4][4];
            #pragma unroll
            for (int mi = 0; mi < 4; mi++) {
                uint32_t addr = aB +
                    ((warp_m * 64 + mi * 16 + a_r) * ROW_HALFS + ks * 16 + a_k8 * 8) * 2;
                ldm4(a[mi][0], a[mi][1], a[mi][2], a[mi][3], addr);
            }
            uint32_t b[4][2];
            #pragma unroll
            for (int j = 0; j < 2; j++) {
                uint32_t addr = bB +
                    ((warp_n * 32 + (2 * j + b_t) * 8 + b_r) * ROW_HALFS + ks * 16 + b_k8 * 8) * 2;
                ldm4(b[2 * j][0], b[2 * j][1], b[2 * j + 1][0], b[2 * j + 1][1], addr);
            }
            #pragma unroll
            for (int mi = 0; mi < 4; mi++)
                #pragma unroll
                for (int ni = 0; ni < 4; ni++)
                    mma16816(acc[mi][ni][0], acc[mi][ni][1], acc[mi][ni][2], acc[mi][ni][3],
                             a[mi][0], a[mi][1], a[mi][2], a[mi][3],
                             b[ni][0], b[ni][1]);
        }
    }

    // ---------------- epilogue ----------------
    const int qr = lid >> 2;              // 0..7
    const int qc = (lid & 3) * 2;         // 0,2,4,6
    #pragma unroll
    for (int mi = 0; mi < 4; mi++) {
        #pragma unroll
        for (int half = 0; half < 2; half++) {
            const int r = blockIdx.y * BM + warp_m * 64 + mi * 16 + qr + half * 8;
            #pragma unroll
            for (int ni = 0; ni < 4; ni++) {
                const int c = blockIdx.x * BN + warp_n * 32 + ni * 8 + qc;
                float f0 = acc[mi][ni][half * 2 + 0];
                float f1 = acc[mi][ni][half * 2 + 1];
                if (MODE == 2) {
                    float2 o = {f0 * alpha, f1 * alpha};
                    *reinterpret_cast<float2*>(Cf + (size_t)r * N + c) = o;
                } else if (MODE == 3) {
                    const float2 b2 = *reinterpret_cast<const float2*>(bias + c);
                    const float2 x2 = *reinterpret_cast<const float2*>(resid + (size_t)r * N + c);
                    float2 o = {f0 + b2.x + x2.x, f1 + b2.y + x2.y};
                    *reinterpret_cast<float2*>(Cf + (size_t)r * N + c) = o;
                } else if (MODE == 4) {
                    *reinterpret_cast<__nv_bfloat162*>(Chi + (size_t)r * N + c) =
                        __halves2bfloat162(__float2bfloat16_rn(f0), __float2bfloat16_rn(f1));
                } else { // MODE 5: plain bf16 transposed write (produces V^T)
                    Chi[(size_t)(c + 0) * Mtot + r] = __float2bfloat16_rn(f0);
                    Chi[(size_t)(c + 1) * Mtot + r] = __float2bfloat16_rn(f1);
                }
            }
        }
    }
}

// ---------------- fp32 -> bf16 convert (single tensor) ----------------
__global__ __launch_bounds__(256) void cvt_bf16(
    const float* __restrict__ src, __nv_bfloat16* __restrict__ dst, int n4)
{
    int i = blockIdx.x * 256 + threadIdx.x;
    if (i >= n4) return;
    float4 v = reinterpret_cast<const float4*>(src)[i];
    reinterpret_cast<__nv_bfloat162*>(dst)[i * 2 + 0] =
        __halves2bfloat162(__float2bfloat16_rn(v.x), __float2bfloat16_rn(v.y));
    reinterpret_cast<__nv_bfloat162*>(dst)[i * 2 + 1] =
        __halves2bfloat162(__float2bfloat16_rn(v.z), __float2bfloat16_rn(v.w));
}

// ---------------- fp32 -> bf16 convert (4 weight tensors, one launch) -------
__global__ __launch_bounds__(256) void cvt_bf16_w4(
    const float* __restrict__ s0, const float* __restrict__ s1,
    const float* __restrict__ s2, const float* __restrict__ s3,
    __nv_bfloat16* __restrict__ d0, __nv_bfloat16* __restrict__ d1,
    __nv_bfloat16* __restrict__ d2, __nv_bfloat16* __restrict__ d3, int n4)
{
    const float* src = blockIdx.y == 0 ? s0 : blockIdx.y == 1 ? s1 : blockIdx.y == 2 ? s2 : s3;
    __nv_bfloat16* dst = blockIdx.y == 0 ? d0 : blockIdx.y == 1 ? d1 : blockIdx.y == 2 ? d2 : d3;
    int i = blockIdx.x * 256 + threadIdx.x;
    if (i >= n4) return;
    float4 v = reinterpret_cast<const float4*>(src)[i];
    reinterpret_cast<__nv_bfloat162*>(dst)[i * 2 + 0] =
        __halves2bfloat162(__float2bfloat16_rn(v.x), __float2bfloat16_rn(v.y));
    reinterpret_cast<__nv_bfloat162*>(dst)[i * 2 + 1] =
        __halves2bfloat162(__float2bfloat16_rn(v.z), __float2bfloat16_rn(v.w));
}

// ---------------- row softmax: fp32 scores -> bf16 probs ----------------
__global__ __launch_bounds__(256) void softmax_hi(
    const float* __restrict__ S, __nv_bfloat16* __restrict__ Phi)
{
    __shared__ float red[8];
    const int tid = threadIdx.x;
    const float* p = S + (size_t)blockIdx.x * BATCH;

    float4 v[4];
    float m = -1e30f;
    #pragma unroll
    for (int i = 0; i < 4; i++) {
        v[i] = *reinterpret_cast<const float4*>(p + (size_t)(i * 256 + tid) * 4);
        m = fmaxf(m, fmaxf(fmaxf(v[i].x, v[i].y), fmaxf(v[i].z, v[i].w)));
    }
    #pragma unroll
    for (int o = 16; o; o >>= 1) m = fmaxf(m, __shfl_xor_sync(0xffffffffu, m, o));
    if ((tid & 31) == 0) red[tid >> 5] = m;
    __syncthreads();
    m = red[0];
    #pragma unroll
    for (int i = 1; i < 8; i++) m = fmaxf(m, red[i]);
    __syncthreads();

    float s = 0.f;
    #pragma unroll
    for (int i = 0; i < 4; i++) {
        v[i].x = __expf(v[i].x - m); v[i].y = __expf(v[i].y - m);
        v[i].z = __expf(v[i].z - m); v[i].w = __expf(v[i].w - m);
        s += v[i].x + v[i].y + v[i].z + v[i].w;
    }
    #pragma unroll
    for (int o = 16; o; o >>= 1) s += __shfl_xor_sync(0xffffffffu, s, o);
    if ((tid & 31) == 0) red[tid >> 5] = s;
    __syncthreads();
    s = red[0];
    #pragma unroll
    for (int i = 1; i < 8; i++) s += red[i];
    const float rinv = 1.f / s;

    __nv_bfloat16* phr = Phi + (size_t)blockIdx.x * BATCH;
    #pragma unroll
    for (int i = 0; i < 4; i++) {
        const int e0 = (i * 256 + tid) * 4;
        reinterpret_cast<__nv_bfloat162*>(phr + e0)[0] = __halves2bfloat162(
            __float2bfloat16_rn(v[i].x * rinv), __float2bfloat16_rn(v[i].y * rinv));
        reinterpret_cast<__nv_bfloat162*>(phr + e0)[1] = __halves2bfloat162(
            __float2bfloat16_rn(v[i].z * rinv), __float2bfloat16_rn(v[i].w * rinv));
    }
}

// ---------------- layernorm ----------------
__global__ __launch_bounds__(256) void layernorm_rows(
    const float* __restrict__ H, const float* __restrict__ gamma,
    const float* __restrict__ beta, float* __restrict__ out)
{
    __shared__ float redS[8], redQ[8];
    const int tid = threadIdx.x;
    const float* p = H + (size_t)blockIdx.x * DIM;

    float4 v = *reinterpret_cast<const float4*>(p + tid * 4);
    float s  = v.x + v.y + v.z + v.w;
    float ss = v.x * v.x + v.y * v.y + v.z * v.z + v.w * v.w;
    #pragma unroll
    for (int o = 16; o; o >>= 1) {
        s  += __shfl_xor_sync(0xffffffffu, s, o);
        ss += __shfl_xor_sync(0xffffffffu, ss, o);
    }
    if ((tid & 31) == 0) { redS[tid >> 5] = s; redQ[tid >> 5] = ss; }
    __syncthreads();
    s = 0.f; ss = 0.f;
    #pragma unroll
    for (int i = 0; i < 8; i++) { s += redS[i]; ss += redQ[i]; }

    const float mu  = s * (1.f / DIM);
    const float var = ss * (1.f / DIM) - mu * mu;
    const float rs  = rsqrtf(var + LN_EPS);

    float4 g = *reinterpret_cast<const float4*>(gamma + tid * 4);
    float4 b = *reinterpret_cast<const float4*>(beta  + tid * 4);
    float4 o;
    o.x = (v.x - mu) * rs * g.x + b.x;
    o.y = (v.y - mu) * rs * g.y + b.y;
    o.z = (v.z - mu) * rs * g.z + b.z;
    o.w = (v.w - mu) * rs * g.w + b.w;
    *reinterpret_cast<float4*>(out + (size_t)blockIdx.x * DIM + tid * 4) = o;
}

// ---------------- launch ----------------
extern "C" void kernel_launch(void* const* d_in, const int* in_sizes, int n_in,
                              void* d_out, int out_size)
{
    const float* x     = (const float*)d_in[0];
    const float* Wq    = (const float*)d_in[1];
    const float* Wk    = (const float*)d_in[2];
    const float* Wv    = (const float*)d_in[3];
    const float* fcw   = (const float*)d_in[4];
    const float* fcb   = (const float*)d_in[5];
    const float* gamma = (const float*)d_in[6];
    const float* beta  = (const float*)d_in[7];
    float* out = (float*)d_out;

    __nv_bfloat16 *xhi, *wqhi, *wkhi, *wvhi, *fwhi;
    __nv_bfloat16 *qhi, *khi, *vthi, *phi, *avhi;
    float *sc, *h;
    cudaGetSymbolAddress((void**)&xhi,  g_xhi);
    cudaGetSymbolAddress((void**)&wqhi, g_wqhi);
    cudaGetSymbolAddress((void**)&wkhi, g_wkhi);
    cudaGetSymbolAddress((void**)&wvhi, g_wvhi);
    cudaGetSymbolAddress((void**)&fwhi, g_fwhi);
    cudaGetSymbolAddress((void**)&qhi,  g_qhi);
    cudaGetSymbolAddress((void**)&khi,  g_khi);
    cudaGetSymbolAddress((void**)&vthi, g_vthi);
    cudaGetSymbolAddress((void**)&phi,  g_phi);
    cudaGetSymbolAddress((void**)&avhi, g_avhi);
    cudaGetSymbolAddress((void**)&sc,   g_s);
    cudaGetSymbolAddress((void**)&h,    g_h);

    cudaFuncSetAttribute(gemm_mma<4,1>, cudaFuncAttributeMaxDynamicSharedMemorySize, SMEM_TOTAL);
    cudaFuncSetAttribute(gemm_mma<5,1>, cudaFuncAttributeMaxDynamicSharedMemorySize, SMEM_TOTAL);
    cudaFuncSetAttribute(gemm_mma<2,1>, cudaFuncAttributeMaxDynamicSharedMemorySize, SMEM_TOTAL);
    cudaFuncSetAttribute(gemm_mma<3,1>, cudaFuncAttributeMaxDynamicSharedMemorySize, SMEM_TOTAL);

    // convert inputs to bf16
    const int nX = BATCH * DIM / 4, nW = DIM * DIM / 4;
    cvt_bf16<<<(nX + 255) / 256, 256>>>(x, xhi, nX);
    cvt_bf16_w4<<<dim3((nW + 255) / 256, 4), 256>>>(Wq, Wk, Wv, fcw,
                                                    wqhi, wkhi, wvhi, fwhi, nW);

    const dim3 blk(256);
    const dim3 gP(DIM / BN,   BATCH / BM);   // 8 x 32
    const dim3 gS(BATCH / BN, BATCH / BM);   // 32 x 32

    // q = x@Wq^T, k = x@Wk^T (bf16 out); v = x@Wv^T (bf16, transposed out)
    gemm_mma<4,1><<<gP, blk, SMEM_TOTAL>>>(xhi, nullptr, wqhi, DIM, DIM, BATCH, 1.f,
                                           nullptr, qhi, nullptr, nullptr);
    gemm_mma<4,1><<<gP, blk, SMEM_TOTAL>>>(xhi, nullptr, wkhi, DIM, DIM, BATCH, 1.f,
                                           nullptr, khi, nullptr, nullptr);
    gemm_mma<5,1><<<gP, blk, SMEM_TOTAL>>>(xhi, nullptr, wvhi, DIM, DIM, BATCH, 1.f,
                                           nullptr, vthi, nullptr, nullptr);

    // scores = (k @ q^T) / 32   (single pass, fp32 out)
    gemm_mma<2,1><<<gS, blk, SMEM_TOTAL>>>(khi, nullptr, qhi, DIM, BATCH, BATCH, 0.03125f,
                                           sc, nullptr, nullptr, nullptr);

    // softmax -> probs bf16
    softmax_hi<<<BATCH, 256>>>(sc, phi);

    // av = attn @ v  (B = v^T, K = 4096, bf16 out)
    gemm_mma<4,1><<<gP, blk, SMEM_TOTAL>>>(phi, nullptr, vthi, BATCH, DIM, BATCH, 1.f,
                                           nullptr, avhi, nullptr, nullptr);

    // h = av @ fcw^T + fcb + x  (fp32 out)
    gemm_mma<3,1><<<gP, blk, SMEM_TOTAL>>>(avhi, nullptr, fwhi, DIM, DIM, BATCH, 1.f,
                                           h, nullptr, fcb, x);

    // layernorm -> out
    layernorm_rows<<<BATCH, 256>>>(h, gamma, beta, out);
}